// round 13
// baseline (speedup 1.0000x reference)
#include <cuda_runtime.h>
#include <cuda_fp16.h>
#include <cstdint>

#define Nn 2048
#define Mm 10
#define Dd 256
#define ROWS (Nn * Mm)      // 20480
#define NCTA_GEMM ((Nn / 128) * (ROWS / 128))   // 2560

// ---------------------------------------------------------------------------
// Scratch (device globals; no allocation allowed)
// ---------------------------------------------------------------------------
__device__ __align__(16) __half g_A[(size_t)ROWS * Dd];  // normalized emb, fp16
__device__ __align__(16) __half g_B[(size_t)Nn * Dd];    // normalized centroids, fp16
__device__ float g_rowsum[ROWS];
__device__ float g_pos[ROWS];   // stores t = |w|*(cos-1); shift cancels in lse-pos
__device__ unsigned int g_done; // last-CTA-done counter (reset by last CTA)

__device__ __forceinline__ uint32_t smem_u32(const void* p) {
    uint32_t a;
    asm("{ .reg .u64 t; cvta.to.shared.u64 t, %1; cvt.u32.u64 %0, t; }" : "=r"(a) : "l"(p));
    return a;
}
__device__ __forceinline__ void cpa16(uint32_t dst, const void* src) {
    asm volatile("cp.async.cg.shared.global [%0], [%1], 16;" :: "r"(dst), "l"(src));
}
__device__ __forceinline__ void ldm_x4(uint32_t* r, uint32_t addr) {
    asm volatile("ldmatrix.sync.aligned.m8n8.x4.shared.b16 {%0,%1,%2,%3}, [%4];"
                 : "=r"(r[0]), "=r"(r[1]), "=r"(r[2]), "=r"(r[3]) : "r"(addr));
}
__device__ __forceinline__ void mma_f16acc(uint32_t* c, const uint32_t* a,
                                           uint32_t b0, uint32_t b1) {
    asm volatile(
        "mma.sync.aligned.m16n8k16.row.col.f16.f16.f16.f16 "
        "{%0,%1}, {%2,%3,%4,%5}, {%6,%7}, {%0,%1};"
        : "+r"(c[0]), "+r"(c[1])
        : "r"(a[0]), "r"(a[1]), "r"(a[2]), "r"(a[3]), "r"(b0), "r"(b1));
}
__device__ __forceinline__ float wred32(float v) {
#pragma unroll
    for (int off = 16; off > 0; off >>= 1) v += __shfl_xor_sync(0xffffffffu, v, off);
    return v;
}

// ---------------------------------------------------------------------------
// Kernel 1: prep, 2 warps per speaker (each owns a 128-component half).
// 21 scalar reductions (10 row norms, 1 centroid norm, 10 pos dots) via
// warp partials + one smem exchange + one 64-thread named barrier.
// ---------------------------------------------------------------------------
__global__ void __launch_bounds__(512) prep_kernel(const float* __restrict__ emb,
                                                   const float* __restrict__ wp) {
    const int tid = threadIdx.x;
    const int warp = tid >> 5, lane = tid & 31;
    const int p = warp >> 1;          // pair 0..7 (speaker within block)
    const int h = warp & 1;           // half 0/1 of D
    const int n = blockIdx.x * 8 + p;
    __shared__ float part[8][2][24];  // 21 used, padded

    const int base = h * 128 + lane * 4;     // component offset (4 floats/lane)
    float4 x[Mm];
    const float* src = emb + (size_t)n * Mm * Dd + base;
#pragma unroll
    for (int m = 0; m < Mm; m++) x[m] = *(const float4*)(src + m * Dd);

    // centroid per-lane raw sums
    float s0 = 0, s1 = 0, s2 = 0, s3 = 0;
#pragma unroll
    for (int m = 0; m < Mm; m++) {
        s0 += x[m].x; s1 += x[m].y; s2 += x[m].z; s3 += x[m].w;
    }

    // warp partials: row norms, centroid norm, pos dots
#pragma unroll
    for (int m = 0; m < Mm; m++) {
        float ss = wred32(x[m].x * x[m].x + x[m].y * x[m].y
                        + x[m].z * x[m].z + x[m].w * x[m].w);
        if (lane == 0) part[p][h][m] = ss;
    }
    {
        float cs = wred32(s0 * s0 + s1 * s1 + s2 * s2 + s3 * s3);
        if (lane == 0) part[p][h][10] = cs;
    }
#pragma unroll
    for (int m = 0; m < Mm; m++) {
        float d = wred32(x[m].x * s0 + x[m].y * s1 + x[m].z * s2 + x[m].w * s3);
        if (lane == 0) part[p][h][11 + m] = d;
    }
    asm volatile("bar.sync %0, 64;" :: "r"(p + 1) : "memory");

    const float cinv = 1.f / fmaxf(sqrtf(part[p][0][10] + part[p][1][10]), 1e-12f);

    // normalized rows -> fp16
#pragma unroll
    for (int m = 0; m < Mm; m++) {
        float s = 1.f / fmaxf(sqrtf(part[p][0][m] + part[p][1][m]), 1e-12f);
        __half2 h0 = __floats2half2_rn(x[m].x * s, x[m].y * s);
        __half2 h1 = __floats2half2_rn(x[m].z * s, x[m].w * s);
        uint2 v{*(uint32_t*)&h0, *(uint32_t*)&h1};
        *(uint2*)(g_A + (size_t)(n * Mm + m) * Dd + base) = v;
    }
    // centroid -> fp16
    {
        __half2 h0 = __floats2half2_rn(s0 * cinv, s1 * cinv);
        __half2 h1 = __floats2half2_rn(s2 * cinv, s3 * cinv);
        uint2 v{*(uint32_t*)&h0, *(uint32_t*)&h1};
        *(uint2*)(g_B + (size_t)n * Dd + base) = v;
    }
    // pos + rowsum zero (warp h==0, lane<Mm)
    if (h == 0 && lane < Mm) {
        float wabs = fabsf(*wp);
        float sc = 1.f / fmaxf(sqrtf(part[p][0][lane] + part[p][1][lane]), 1e-12f);
        float d = part[p][0][11 + lane] + part[p][1][11 + lane];
        g_pos[n * Mm + lane] = wabs * (d * sc * cinv - 1.f);
        g_rowsum[n * Mm + lane] = 0.f;
    }
}

// ---------------------------------------------------------------------------
// Kernel 2: fp16 HMMA (fp16 acc), CTA tile 128x128, 4 warps (2x2), warp tile
// 64x64, BK=32, 2-stage cp.async pipeline, 4 CTAs/SM. Fused exp epilogue,
// then last-CTA-done final loss reduction (no third kernel).
// ---------------------------------------------------------------------------
#define BK 32
#define SSTR 40                       // padded row stride (elems); 80B
#define NCHUNK (Dd / BK)              // 8
#define STG (128 * SSTR * 2)          // 10240 B per tile stage

__global__ void __launch_bounds__(128, 4)
gemm_lse_kernel(const float* __restrict__ wp, float* __restrict__ out) {
    __shared__ __half smem[2 * 2 * STG / 2];   // 40960 B: [A0 A1 | B0 B1]
    __shared__ float lred[4];
    __shared__ bool is_last;
    const uint32_t as0 = smem_u32(smem);
    const uint32_t bs0 = as0 + 2 * STG;

    const int tid = threadIdx.x;
    const int wid = tid >> 5, lane = tid & 31;
    const int wm = wid >> 1;          // 0..1  (64-row slice)
    const int wn = wid & 1;           // 0..1  (64-col slice)
    const int r0 = blockIdx.y * 128;
    const int c0 = blockIdx.x * 128;

    const int lrow = tid >> 2;        // 0..31
    const int lquad = tid & 3;

    auto load_chunk = [&](int c, int stg) {
#pragma unroll
        for (int i = 0; i < 4; i++) {
            int row = lrow + i * 32;
            cpa16(as0 + stg * STG + row * (SSTR * 2) + lquad * 16,
                  g_A + (size_t)(r0 + row) * Dd + c * BK + lquad * 8);
            cpa16(bs0 + stg * STG + row * (SSTR * 2) + lquad * 16,
                  g_B + (size_t)(c0 + row) * Dd + c * BK + lquad * 8);
        }
        asm volatile("cp.async.commit_group;" ::: "memory");
    };

    uint32_t acc[4][8][2] = {};       // fp16x2 accumulators

    load_chunk(0, 0);
    load_chunk(1, 1);

#pragma unroll
    for (int c = 0; c < NCHUNK; c++) {
        if (c < 7) asm volatile("cp.async.wait_group 1;" ::: "memory");
        else       asm volatile("cp.async.wait_group 0;" ::: "memory");
        __syncthreads();

        const uint32_t ab = as0 + (c & 1) * STG;
        const uint32_t bb = bs0 + (c & 1) * STG;
#pragma unroll
        for (int ks = 0; ks < 2; ks++) {
            const int k0 = ks * 16;
            uint32_t a[4][4];
#pragma unroll
            for (int mt = 0; mt < 4; mt++) {
                int row = wm * 64 + mt * 16 + (lane & 15);
                int col = k0 + (lane >> 4) * 8;
                ldm_x4(a[mt], ab + row * (SSTR * 2) + col * 2);
            }
            uint32_t b[4][4];
#pragma unroll
            for (int ng = 0; ng < 4; ng++) {
                int row = wn * 64 + ng * 16 + (lane & 7) + (lane >> 4) * 8;
                int col = k0 + ((lane >> 3) & 1) * 8;
                ldm_x4(b[ng], bb + row * (SSTR * 2) + col * 2);
            }
#pragma unroll
            for (int mt = 0; mt < 4; mt++)
#pragma unroll
                for (int nt = 0; nt < 8; nt++)
                    mma_f16acc(acc[mt][nt], a[mt],
                               b[nt >> 1][(nt & 1) * 2], b[nt >> 1][(nt & 1) * 2 + 1]);
        }
        __syncthreads();               // stage reuse guard (2-stage)
        if (c + 2 < NCHUNK) load_chunk(c + 2, c & 1);
    }

    // ---- fused epilogue (branch-free): rowsum += exp(|w|*(cos-1)) ----
    const float wabs = fabsf(*wp);
    const float nw = -wabs;
    const int q = lane >> 2, qi = lane & 3;

#pragma unroll
    for (int mt = 0; mt < 4; mt++) {
        const int rowA = r0 + wm * 64 + mt * 16 + q;
        const int rowB = rowA + 8;
        float sA = 0.f, sB = 0.f;
#pragma unroll
        for (int nt = 0; nt < 8; nt++) {
            float2 vA = __half22float2(*(__half2*)&acc[mt][nt][0]);
            float2 vB = __half22float2(*(__half2*)&acc[mt][nt][1]);
            sA += __expf(fmaf(wabs, vA.x, nw)) + __expf(fmaf(wabs, vA.y, nw));
            sB += __expf(fmaf(wabs, vB.x, nw)) + __expf(fmaf(wabs, vB.y, nw));
        }
#pragma unroll
        for (int off = 2; off > 0; off >>= 1) {
            sA += __shfl_xor_sync(0xffffffffu, sA, off);
            sB += __shfl_xor_sync(0xffffffffu, sB, off);
        }
        if (qi == 0) {
            atomicAdd(&g_rowsum[rowA], sA);
            atomicAdd(&g_rowsum[rowB], sB);
        }
    }

    // ---- last-CTA-done: final loss reduction in this kernel ----
    __syncthreads();
    if (tid == 0) {
        __threadfence();
        unsigned v = atomicAdd(&g_done, 1u);
        is_last = (v == NCTA_GEMM - 1);
    }
    __syncthreads();
    if (is_last) {
        if (tid == 0) g_done = 0;     // reset for graph replay
        __threadfence();
        float s = 0.f;
        for (int i = tid; i < ROWS / 4; i += 128) {
            float4 rs = *(const float4*)&g_rowsum[i * 4];
            float4 ps = *(const float4*)&g_pos[i * 4];
            s += __logf(rs.x) - ps.x + __logf(rs.y) - ps.y
               + __logf(rs.z) - ps.z + __logf(rs.w) - ps.w;
        }
        s = wred32(s);
        if (lane == 0) lred[wid] = s;
        __syncthreads();
        if (tid == 0)
            out[0] = (lred[0] + lred[1] + lred[2] + lred[3]) / (float)ROWS;
    }
}

// ---------------------------------------------------------------------------
extern "C" void kernel_launch(void* const* d_in, const int* in_sizes, int n_in,
                              void* d_out, int out_size) {
    const float* emb = (const float*)d_in[0];
    const float* w   = (const float*)d_in[1];
    const float* b   = (const float*)d_in[2];
    (void)b;
    float* out = (float*)d_out;

    prep_kernel<<<Nn / 8, 512>>>(emb, w);
    gemm_lse_kernel<<<dim3(Nn / 128, ROWS / 128), 128>>>(w, out);
}

// round 14
// speedup vs baseline: 1.0945x; 1.0945x over previous
#include <cuda_runtime.h>
#include <cuda_fp16.h>
#include <cstdint>

#define Nn 2048
#define Mm 10
#define Dd 256
#define ROWS (Nn * Mm)      // 20480

// ---------------------------------------------------------------------------
// Scratch (device globals; no allocation allowed)
// ---------------------------------------------------------------------------
__device__ __align__(16) __half g_A[(size_t)ROWS * Dd];  // normalized emb, fp16
__device__ __align__(16) __half g_B[(size_t)Nn * Dd];    // normalized centroids, fp16
__device__ float g_rowsum[ROWS];
__device__ float g_pos[ROWS];   // stores t = |w|*(cos-1); shift cancels in lse-pos

__device__ __forceinline__ uint32_t smem_u32(const void* p) {
    uint32_t a;
    asm("{ .reg .u64 t; cvta.to.shared.u64 t, %1; cvt.u32.u64 %0, t; }" : "=r"(a) : "l"(p));
    return a;
}
__device__ __forceinline__ void cpa16(uint32_t dst, const void* src) {
    asm volatile("cp.async.cg.shared.global [%0], [%1], 16;" :: "r"(dst), "l"(src));
}
__device__ __forceinline__ void ldm_x4(uint32_t* r, uint32_t addr) {
    asm volatile("ldmatrix.sync.aligned.m8n8.x4.shared.b16 {%0,%1,%2,%3}, [%4];"
                 : "=r"(r[0]), "=r"(r[1]), "=r"(r[2]), "=r"(r[3]) : "r"(addr));
}
__device__ __forceinline__ void mma_f16acc(uint32_t* c, const uint32_t* a,
                                           uint32_t b0, uint32_t b1) {
    asm volatile(
        "mma.sync.aligned.m16n8k16.row.col.f16.f16.f16.f16 "
        "{%0,%1}, {%2,%3,%4,%5}, {%6,%7}, {%0,%1};"
        : "+r"(c[0]), "+r"(c[1])
        : "r"(a[0]), "r"(a[1]), "r"(a[2]), "r"(a[3]), "r"(b0), "r"(b1));
}
__device__ __forceinline__ float wred32(float v) {
#pragma unroll
    for (int off = 16; off > 0; off >>= 1) v += __shfl_xor_sync(0xffffffffu, v, off);
    return v;
}

// ---------------------------------------------------------------------------
// Kernel 1: prep, 2 warps per speaker (each owns a 128-component half).
// 21 scalar reductions via warp partials + one smem exchange + one
// 64-thread named barrier. fp32-exact pos.
// ---------------------------------------------------------------------------
__global__ void __launch_bounds__(512) prep_kernel(const float* __restrict__ emb,
                                                   const float* __restrict__ wp) {
    const int tid = threadIdx.x;
    const int warp = tid >> 5, lane = tid & 31;
    const int p = warp >> 1;          // pair 0..7 (speaker within block)
    const int h = warp & 1;           // half 0/1 of D
    const int n = blockIdx.x * 8 + p;
    __shared__ float part[8][2][24];  // 21 used, padded

    const int base = h * 128 + lane * 4;
    float4 x[Mm];
    const float* src = emb + (size_t)n * Mm * Dd + base;
#pragma unroll
    for (int m = 0; m < Mm; m++) x[m] = *(const float4*)(src + m * Dd);

    float s0 = 0, s1 = 0, s2 = 0, s3 = 0;
#pragma unroll
    for (int m = 0; m < Mm; m++) {
        s0 += x[m].x; s1 += x[m].y; s2 += x[m].z; s3 += x[m].w;
    }

#pragma unroll
    for (int m = 0; m < Mm; m++) {
        float ss = wred32(x[m].x * x[m].x + x[m].y * x[m].y
                        + x[m].z * x[m].z + x[m].w * x[m].w);
        if (lane == 0) part[p][h][m] = ss;
    }
    {
        float cs = wred32(s0 * s0 + s1 * s1 + s2 * s2 + s3 * s3);
        if (lane == 0) part[p][h][10] = cs;
    }
#pragma unroll
    for (int m = 0; m < Mm; m++) {
        float d = wred32(x[m].x * s0 + x[m].y * s1 + x[m].z * s2 + x[m].w * s3);
        if (lane == 0) part[p][h][11 + m] = d;
    }
    asm volatile("bar.sync %0, 64;" :: "r"(p + 1) : "memory");

    const float cinv = 1.f / fmaxf(sqrtf(part[p][0][10] + part[p][1][10]), 1e-12f);

#pragma unroll
    for (int m = 0; m < Mm; m++) {
        float s = 1.f / fmaxf(sqrtf(part[p][0][m] + part[p][1][m]), 1e-12f);
        __half2 h0 = __floats2half2_rn(x[m].x * s, x[m].y * s);
        __half2 h1 = __floats2half2_rn(x[m].z * s, x[m].w * s);
        uint2 v{*(uint32_t*)&h0, *(uint32_t*)&h1};
        *(uint2*)(g_A + (size_t)(n * Mm + m) * Dd + base) = v;
    }
    {
        __half2 h0 = __floats2half2_rn(s0 * cinv, s1 * cinv);
        __half2 h1 = __floats2half2_rn(s2 * cinv, s3 * cinv);
        uint2 v{*(uint32_t*)&h0, *(uint32_t*)&h1};
        *(uint2*)(g_B + (size_t)n * Dd + base) = v;
    }
    if (h == 0 && lane < Mm) {
        float wabs = fabsf(*wp);
        float sc = 1.f / fmaxf(sqrtf(part[p][0][lane] + part[p][1][lane]), 1e-12f);
        float d = part[p][0][11 + lane] + part[p][1][11 + lane];
        g_pos[n * Mm + lane] = wabs * (d * sc * cinv - 1.f);
        g_rowsum[n * Mm + lane] = 0.f;
    }
}

// ---------------------------------------------------------------------------
// Kernel 2: fp16 HMMA (fp16 acc), CTA tile 128x128, 4 warps (2x2), warp tile
// 64x64, BK=32, 2-stage cp.async pipeline, 4 CTAs/SM. (Exact R12 version —
// the proven 53us configuration; no fused tail.)
// ---------------------------------------------------------------------------
#define BK 32
#define SSTR 40                       // padded row stride (elems); 80B
#define NCHUNK (Dd / BK)              // 8
#define STG (128 * SSTR * 2)          // 10240 B per tile stage

__global__ void __launch_bounds__(128, 4)
gemm_lse_kernel(const float* __restrict__ wp) {
    __shared__ __half smem[2 * 2 * STG / 2];   // 40960 B: [A0 A1 | B0 B1]
    const uint32_t as0 = smem_u32(smem);
    const uint32_t bs0 = as0 + 2 * STG;

    const int tid = threadIdx.x;
    const int wid = tid >> 5, lane = tid & 31;
    const int wm = wid >> 1;
    const int wn = wid & 1;
    const int r0 = blockIdx.y * 128;
    const int c0 = blockIdx.x * 128;

    const int lrow = tid >> 2;
    const int lquad = tid & 3;

    auto load_chunk = [&](int c, int stg) {
#pragma unroll
        for (int i = 0; i < 4; i++) {
            int row = lrow + i * 32;
            cpa16(as0 + stg * STG + row * (SSTR * 2) + lquad * 16,
                  g_A + (size_t)(r0 + row) * Dd + c * BK + lquad * 8);
            cpa16(bs0 + stg * STG + row * (SSTR * 2) + lquad * 16,
                  g_B + (size_t)(c0 + row) * Dd + c * BK + lquad * 8);
        }
        asm volatile("cp.async.commit_group;" ::: "memory");
    };

    uint32_t acc[4][8][2] = {};

    load_chunk(0, 0);
    load_chunk(1, 1);

#pragma unroll
    for (int c = 0; c < NCHUNK; c++) {
        if (c < 7) asm volatile("cp.async.wait_group 1;" ::: "memory");
        else       asm volatile("cp.async.wait_group 0;" ::: "memory");
        __syncthreads();

        const uint32_t ab = as0 + (c & 1) * STG;
        const uint32_t bb = bs0 + (c & 1) * STG;
#pragma unroll
        for (int ks = 0; ks < 2; ks++) {
            const int k0 = ks * 16;
            uint32_t a[4][4];
#pragma unroll
            for (int mt = 0; mt < 4; mt++) {
                int row = wm * 64 + mt * 16 + (lane & 15);
                int col = k0 + (lane >> 4) * 8;
                ldm_x4(a[mt], ab + row * (SSTR * 2) + col * 2);
            }
            uint32_t b[4][4];
#pragma unroll
            for (int ng = 0; ng < 4; ng++) {
                int row = wn * 64 + ng * 16 + (lane & 7) + (lane >> 4) * 8;
                int col = k0 + ((lane >> 3) & 1) * 8;
                ldm_x4(b[ng], bb + row * (SSTR * 2) + col * 2);
            }
#pragma unroll
            for (int mt = 0; mt < 4; mt++)
#pragma unroll
                for (int nt = 0; nt < 8; nt++)
                    mma_f16acc(acc[mt][nt], a[mt],
                               b[nt >> 1][(nt & 1) * 2], b[nt >> 1][(nt & 1) * 2 + 1]);
        }
        __syncthreads();
        if (c + 2 < NCHUNK) load_chunk(c + 2, c & 1);
    }

    const float wabs = fabsf(*wp);
    const float nw = -wabs;
    const int q = lane >> 2, qi = lane & 3;

#pragma unroll
    for (int mt = 0; mt < 4; mt++) {
        const int rowA = r0 + wm * 64 + mt * 16 + q;
        const int rowB = rowA + 8;
        float sA = 0.f, sB = 0.f;
#pragma unroll
        for (int nt = 0; nt < 8; nt++) {
            float2 vA = __half22float2(*(__half2*)&acc[mt][nt][0]);
            float2 vB = __half22float2(*(__half2*)&acc[mt][nt][1]);
            sA += __expf(fmaf(wabs, vA.x, nw)) + __expf(fmaf(wabs, vA.y, nw));
            sB += __expf(fmaf(wabs, vB.x, nw)) + __expf(fmaf(wabs, vB.y, nw));
        }
#pragma unroll
        for (int off = 2; off > 0; off >>= 1) {
            sA += __shfl_xor_sync(0xffffffffu, sA, off);
            sB += __shfl_xor_sync(0xffffffffu, sB, off);
        }
        if (qi == 0) {
            atomicAdd(&g_rowsum[rowA], sA);
            atomicAdd(&g_rowsum[rowB], sB);
        }
    }
}

// ---------------------------------------------------------------------------
// Kernel 3: loss = mean_r( log(rowsum[r]) - pos_t[r] ), 1024 thr, vectorized.
// ---------------------------------------------------------------------------
__global__ void __launch_bounds__(1024) loss_kernel(float* __restrict__ out) {
    __shared__ float red[32];
    const int tid = threadIdx.x;
    float s = 0.f;
#pragma unroll
    for (int i = 0; i < ROWS / 4096; i++) {
        int r4 = tid + i * 1024;
        float4 rs = *(const float4*)&g_rowsum[r4 * 4];
        float4 ps = *(const float4*)&g_pos[r4 * 4];
        s += __logf(rs.x) - ps.x + __logf(rs.y) - ps.y
           + __logf(rs.z) - ps.z + __logf(rs.w) - ps.w;
    }
#pragma unroll
    for (int off = 16; off > 0; off >>= 1) s += __shfl_xor_sync(0xffffffffu, s, off);
    if ((tid & 31) == 0) red[tid >> 5] = s;
    __syncthreads();
    if (tid < 32) {
        float t = red[tid];
#pragma unroll
        for (int off = 16; off > 0; off >>= 1) t += __shfl_xor_sync(0xffffffffu, t, off);
        if (tid == 0) out[0] = t / (float)ROWS;
    }
}

// ---------------------------------------------------------------------------
extern "C" void kernel_launch(void* const* d_in, const int* in_sizes, int n_in,
                              void* d_out, int out_size) {
    const float* emb = (const float*)d_in[0];
    const float* w   = (const float*)d_in[1];
    const float* b   = (const float*)d_in[2];
    (void)b;
    float* out = (float*)d_out;

    prep_kernel<<<Nn / 8, 512>>>(emb, w);
    gemm_lse_kernel<<<dim3(Nn / 128, ROWS / 128), 128>>>(w);
    loss_kernel<<<1, 1024>>>(out);
}